// round 1
// baseline (speedup 1.0000x reference)
#include <cuda_runtime.h>
#include <math.h>

#define T_SEQ   1536
#define DMODEL  2880
#define QKVD    5120
#define NH      64
#define NKV     8
#define HD      64
#define WIN     128
#define NEG_INF -1e30f

// scratch (allocations are forbidden; __device__ globals are the sanctioned path)
__device__ __align__(16) float g_qkv[T_SEQ * QKVD];     // 31.5 MB
__device__ __align__(16) float g_att[T_SEQ * NH * HD];  // 25 MB

// ---------------------------------------------------------------------------
// SGEMM: C[M,N] = A[M,K] @ B[K,N] + bias[N], 128x128x8 tiles, 8x8 microtile
// GUARD_N: bounds-check N (needed for N=2880 which is not a multiple of 128)
// M must be a multiple of 128, K a multiple of 8 (holds for all our shapes).
// ---------------------------------------------------------------------------
template <int GUARD_N>
__global__ __launch_bounds__(256, 2)
void sgemm_bias(int M, int N, int K,
                const float* __restrict__ A, const float* __restrict__ B,
                const float* __restrict__ bias, float* __restrict__ C)
{
    __shared__ float As[8][128];
    __shared__ float Bs[8][128];

    const int tid = threadIdx.x;
    const int bm  = blockIdx.y * 128;
    const int bn  = blockIdx.x * 128;
    const int ty  = tid >> 4;        // 0..15
    const int tx  = tid & 15;        // 0..15

    const int arow = tid >> 1;             // 0..127
    const int acol = (tid & 1) * 4;        // 0 or 4
    const int brow = tid >> 5;             // 0..7
    const int bcol = (tid & 31) * 4;       // 0..124
    const bool bok = (!GUARD_N) || (bn + bcol < N);

    const float* Ap = A + (size_t)(bm + arow) * K + acol;
    const float* Bp = B + (size_t)brow * N + bn + bcol;

    float acc[8][8];
    #pragma unroll
    for (int i = 0; i < 8; i++)
        #pragma unroll
        for (int j = 0; j < 8; j++) acc[i][j] = 0.0f;

    const int ntiles = K >> 3;
    for (int kt = 0; kt < ntiles; kt++) {
        float4 a4 = *(const float4*)Ap;
        float4 b4 = bok ? *(const float4*)Bp : make_float4(0.f, 0.f, 0.f, 0.f);
        Ap += 8;
        Bp += (size_t)8 * N;

        As[acol + 0][arow] = a4.x;
        As[acol + 1][arow] = a4.y;
        As[acol + 2][arow] = a4.z;
        As[acol + 3][arow] = a4.w;
        *(float4*)&Bs[brow][bcol] = b4;
        __syncthreads();

        #pragma unroll
        for (int kk = 0; kk < 8; kk++) {
            float ar[8], br[8];
            *(float4*)&ar[0] = *(const float4*)&As[kk][ty * 8];
            *(float4*)&ar[4] = *(const float4*)&As[kk][ty * 8 + 4];
            *(float4*)&br[0] = *(const float4*)&Bs[kk][tx * 8];
            *(float4*)&br[4] = *(const float4*)&Bs[kk][tx * 8 + 4];
            #pragma unroll
            for (int i = 0; i < 8; i++)
                #pragma unroll
                for (int j = 0; j < 8; j++)
                    acc[i][j] = fmaf(ar[i], br[j], acc[i][j]);
        }
        __syncthreads();
    }

    #pragma unroll
    for (int i = 0; i < 8; i++) {
        const int row = bm + ty * 8 + i;
        #pragma unroll
        for (int j4 = 0; j4 < 2; j4++) {
            const int col = bn + tx * 8 + j4 * 4;
            if (GUARD_N && col >= N) continue;
            float4 bs = *(const float4*)&bias[col];
            float4 r;
            r.x = acc[i][j4 * 4 + 0] + bs.x;
            r.y = acc[i][j4 * 4 + 1] + bs.y;
            r.z = acc[i][j4 * 4 + 2] + bs.z;
            r.w = acc[i][j4 * 4 + 3] + bs.w;
            *(float4*)&C[(size_t)row * N + col] = r;
        }
    }
}

// ---------------------------------------------------------------------------
// YaRN RoPE applied in place to q (cols [0,4096)) and k (cols [4096,4608))
// of the qkv buffer. One thread per (t, head, rotation pair).
// inv_freq computed in double (matches numpy to fp32 rounding), angle and
// rotation in fp32 exactly as the reference's fp32 outer product.
// ---------------------------------------------------------------------------
__global__ void rope_kernel(float* __restrict__ qkv)
{
    const int gid = blockIdx.x * blockDim.x + threadIdx.x;
    const int i   = gid & 31;              // pair index 0..31
    const int hh  = (gid >> 5) % 72;       // 0..63 = q heads, 64..71 = k heads
    const int t   = gid / (32 * 72);
    if (t >= T_SEQ) return;

    const double TWO_PI = 6.283185307179586;
    double freq = pow(150000.0, (double)(2 * i) / 64.0);
    double conc = 0.1 * log(32.0) + 1.0;
    double lo   = 32.0 * log(1024.0 / (32.0 * TWO_PI)) / log(150000.0);
    double hi   = 32.0 * log(1024.0 / TWO_PI) / log(150000.0);
    double ramp = ((double)i - lo) / (hi - lo);
    ramp = fmin(1.0, fmax(0.0, ramp));
    double invf = ramp / (32.0 * freq) + (1.0 - ramp) / freq;

    const float invf32 = (float)invf;
    const float ang    = (float)t * invf32;   // fp32 product, like the reference
    const float c      = cosf(ang) * (float)conc;
    const float s      = sinf(ang) * (float)conc;

    const int col = (hh < 64) ? hh * 64 : 4096 + (hh - 64) * 64;
    float* p = qkv + (size_t)t * QKVD + col;
    const float x1 = p[i];
    const float x2 = p[i + 32];
    p[i]      = x1 * c - x2 * s;
    p[i + 32] = x2 * c + x1 * s;
}

// ---------------------------------------------------------------------------
// Sliding-window GQA attention with sink logits.
// One CTA per (query position i, kv head). 128 threads.
//  - K window staged in smem with +1 pad (conflict-free column reads)
//  - logits: thread t <-> key j0+t, 8 q-heads per thread
//  - softmax: 4 warps reduce 2 heads each (max, sum, + exp(sink - max))
//  - output: thread t <-> (head m = t/16, 4 dims), V streamed via L1 (8x reuse)
// ---------------------------------------------------------------------------
__global__ __launch_bounds__(128)
void attn_kernel(const float* __restrict__ qkv, const float* __restrict__ sinks,
                 float* __restrict__ att)
{
    __shared__ float Ks[WIN][HD + 1];
    __shared__ float wbuf[8][WIN];
    __shared__ float qs[8][HD];
    __shared__ float mxs[8], rds[8];

    const int i   = blockIdx.x;
    const int hkv = blockIdx.y;
    const int tid = threadIdx.x;

    int j0 = i - (WIN - 1);
    if (j0 < 0) j0 = 0;
    const int nk = i - j0 + 1;            // 1..128 valid keys

    // q: 8 heads x 64 dims = 512 contiguous floats
    {
        const float* qp = qkv + (size_t)i * QKVD + hkv * 8 * 64;
        ((float4*)qs)[tid] = ((const float4*)qp)[tid];
    }
    // K window -> smem (coalesced rows of 64)
    for (int idx = tid; idx < nk * 64; idx += 128) {
        const int j = idx >> 6, d = idx & 63;
        Ks[j][d] = qkv[(size_t)(j0 + j) * QKVD + 4096 + hkv * 64 + d];
    }
    __syncthreads();

    // logits
    float acc[8] = {0.f, 0.f, 0.f, 0.f, 0.f, 0.f, 0.f, 0.f};
    if (tid < nk) {
        #pragma unroll 8
        for (int d = 0; d < 64; d++) {
            const float kd = Ks[tid][d];
            #pragma unroll
            for (int m = 0; m < 8; m++) acc[m] = fmaf(kd, qs[m][d], acc[m]);
        }
    }
    #pragma unroll
    for (int m = 0; m < 8; m++)
        wbuf[m][tid] = (tid < nk) ? acc[m] * 0.125f : NEG_INF;
    __syncthreads();

    // per-head softmax stats: warp w handles heads 2w, 2w+1
    const int lane = tid & 31, wrp = tid >> 5;
    #pragma unroll
    for (int r = 0; r < 2; r++) {
        const int m = wrp * 2 + r;
        const float v0 = wbuf[m][lane],      v1 = wbuf[m][lane + 32];
        const float v2 = wbuf[m][lane + 64], v3 = wbuf[m][lane + 96];
        float mx = fmaxf(fmaxf(v0, v1), fmaxf(v2, v3));
        #pragma unroll
        for (int o = 16; o; o >>= 1) mx = fmaxf(mx, __shfl_xor_sync(0xffffffffu, mx, o));
        float sm = expf(v0 - mx) + expf(v1 - mx) + expf(v2 - mx) + expf(v3 - mx);
        #pragma unroll
        for (int o = 16; o; o >>= 1) sm += __shfl_xor_sync(0xffffffffu, sm, o);
        if (lane == 0) {
            const float denom = sm + expf(sinks[hkv * 8 + m] - mx);
            mxs[m] = mx;
            rds[m] = 1.0f / denom;
        }
    }
    __syncthreads();

    #pragma unroll
    for (int m = 0; m < 8; m++)
        wbuf[m][tid] = expf(wbuf[m][tid] - mxs[m]) * rds[m];   // 0 for tid >= nk
    __syncthreads();

    // O = W @ V : thread -> (head m, 4 output dims)
    const int m  = tid >> 4;
    const int db = (tid & 15) * 4;
    float4 o = make_float4(0.f, 0.f, 0.f, 0.f);
    const float* vcol = qkv + 4608 + hkv * 64 + db;
    for (int j = 0; j < nk; j++) {
        const float wv = wbuf[m][j];
        const float4 v4 = *(const float4*)(vcol + (size_t)(j0 + j) * QKVD);
        o.x = fmaf(wv, v4.x, o.x);
        o.y = fmaf(wv, v4.y, o.y);
        o.z = fmaf(wv, v4.z, o.z);
        o.w = fmaf(wv, v4.w, o.w);
    }
    *(float4*)(att + (size_t)i * (NH * HD) + (hkv * 8 + m) * 64 + db) = o;
}

// ---------------------------------------------------------------------------
extern "C" void kernel_launch(void* const* d_in, const int* in_sizes, int n_in,
                              void* d_out, int out_size)
{
    (void)in_sizes; (void)n_in; (void)out_size;
    const float* x     = (const float*)d_in[0];
    const float* Wqkv  = (const float*)d_in[1];
    const float* bqkv  = (const float*)d_in[2];
    const float* Wout  = (const float*)d_in[3];
    const float* bout  = (const float*)d_in[4];
    const float* sinks = (const float*)d_in[5];
    float* out = (float*)d_out;

    void *qkv_p, *att_p;
    cudaGetSymbolAddress(&qkv_p, g_qkv);
    cudaGetSymbolAddress(&att_p, g_att);
    float* qkv = (float*)qkv_p;
    float* att = (float*)att_p;

    // 1) qkv = x @ W_qkv + b_qkv          (1536x2880 @ 2880x5120)
    sgemm_bias<0><<<dim3(QKVD / 128, T_SEQ / 128), 256>>>(
        T_SEQ, QKVD, DMODEL, x, Wqkv, bqkv, qkv);

    // 2) RoPE in place on q and k
    rope_kernel<<<(T_SEQ * 72 * 32) / 256, 256>>>(qkv);

    // 3) attention -> att (1536 x 4096)
    attn_kernel<<<dim3(T_SEQ, NKV), 128>>>(qkv, sinks, att);

    // 4) out = att @ W_out + b_out        (1536x4096 @ 4096x2880, N guarded)
    sgemm_bias<1><<<dim3((DMODEL + 127) / 128, T_SEQ / 128), 256>>>(
        T_SEQ, DMODEL, NH * HD, att, Wout, bout, out);
}

// round 3
// speedup vs baseline: 3.2513x; 3.2513x over previous
#include <cuda_runtime.h>
#include <cuda_bf16.h>
#include <math.h>
#include <stdint.h>

#define T_SEQ   1536
#define DMODEL  2880
#define QKVD    5120
#define NH      64
#define NKV     8
#define HD      64
#define WIN     128
#define NEG_INF -1e30f
#define N2PAD   2944              // W_out N padded to 23*128

// ---------------------------------------------------------------------------
// scratch (__device__ globals; allocation APIs are forbidden)
// ---------------------------------------------------------------------------
__device__ __align__(16) float g_qkv[T_SEQ * QKVD];
__device__ __align__(16) float g_att[T_SEQ * NH * HD];
__device__ __align__(16) __nv_bfloat16 g_xhi[T_SEQ * DMODEL];
__device__ __align__(16) __nv_bfloat16 g_xlo[T_SEQ * DMODEL];
__device__ __align__(16) __nv_bfloat16 g_w1hi[QKVD * DMODEL];     // [N=5120, K=2880]
__device__ __align__(16) __nv_bfloat16 g_w1lo[QKVD * DMODEL];
__device__ __align__(16) __nv_bfloat16 g_w2hi[N2PAD * (NH * HD)]; // [N=2944, K=4096]
__device__ __align__(16) __nv_bfloat16 g_w2lo[N2PAD * (NH * HD)];
__device__ __align__(16) __nv_bfloat16 g_ahi[T_SEQ * NH * HD];
__device__ __align__(16) __nv_bfloat16 g_alo[T_SEQ * NH * HD];
__device__ float g_invf[32];
__device__ float g_conc;

// ---------------------------------------------------------------------------
// PTX helpers (sm_80+ instructions only — the harness lowers to compute_103,
// which rejects tcgen05/arch-specific PTX)
// ---------------------------------------------------------------------------
__device__ __forceinline__ uint32_t smem_u32(const void* p) {
    uint32_t a;
    asm("{ .reg .u64 t; cvta.to.shared.u64 t, %1; cvt.u32.u64 %0, t; }" : "=r"(a) : "l"(p));
    return a;
}
#define CP_ASYNC16(dst, src) \
    asm volatile("cp.async.cg.shared.global [%0], [%1], 16;" :: "r"(dst), "l"(src))
#define CP_COMMIT() asm volatile("cp.async.commit_group;" ::: "memory")
#define CP_WAIT(n)  asm volatile("cp.async.wait_group %0;" :: "n"(n) : "memory")
#define LDSM4(r0, r1, r2, r3, addr) \
    asm volatile("ldmatrix.sync.aligned.m8n8.x4.shared.b16 {%0,%1,%2,%3}, [%4];" \
        : "=r"(r0), "=r"(r1), "=r"(r2), "=r"(r3) : "r"(addr))
#define MMA16816(d, a, b) \
    asm volatile("mma.sync.aligned.m16n8k16.row.col.f32.bf16.bf16.f32 " \
        "{%0,%1,%2,%3}, {%4,%5,%6,%7}, {%8,%9}, {%0,%1,%2,%3};" \
        : "+f"((d)[0]), "+f"((d)[1]), "+f"((d)[2]), "+f"((d)[3]) \
        : "r"((a)[0]), "r"((a)[1]), "r"((a)[2]), "r"((a)[3]), "r"((b)[0]), "r"((b)[1]))

// smem geometry: 4 tiles per stage (Ah, Al, Bh, Bl), each 128 rows x 80B
#define ROW_B   80
#define TILE_B  (128 * ROW_B)          // 10240
#define STAGE_B (4 * TILE_B)           // 40960
#define GEMM_SMEM (2 * STAGE_B)        // 81920

// ---------------------------------------------------------------------------
// HMMA bf16-split GEMM: C[M,N] = (Ahi+Alo)[M,K] @ (Bhi+Blo)[N,K]^T + bias
// 3 products (hh + hl + lh), fp32 accumulators. 128x128 tile, 256 threads,
// K-chunk 32, cp.async double buffer. M % 128 == 0, K % 32 == 0. B buffer
// must have >= gridDim.x*128 rows (pad rows zero). GUARD_N bounds C stores.
// ---------------------------------------------------------------------------
template <int GUARD_N>
__global__ __launch_bounds__(256, 1)
void gemm_hmma(int M, int N, int K,
               const __nv_bfloat16* __restrict__ Ahi, const __nv_bfloat16* __restrict__ Alo,
               const __nv_bfloat16* __restrict__ Bhi, const __nv_bfloat16* __restrict__ Blo,
               const float* __restrict__ bias, float* __restrict__ C)
{
    extern __shared__ char smem[];
    const uint32_t sb = smem_u32(smem);
    const int tid = threadIdx.x;
    const int wid = tid >> 5, lane = tid & 31;
    const int wm = wid & 1, wn = wid >> 1;          // 2 x 4 warp grid
    const int bm = blockIdx.y * 128, bn = blockIdx.x * 128;

    // cp.async per-thread assignment: row = tid>>1, 32B half-row = (tid&1)
    const int ld_row  = tid >> 1;
    const int ld_half = tid & 1;
    const uint32_t ld_dst = sb + ld_row * ROW_B + ld_half * 32;
    const size_t a_off = (size_t)(bm + ld_row) * K + ld_half * 16;
    const size_t b_off = (size_t)(bn + ld_row) * K + ld_half * 16;

    // ldmatrix per-lane addresses
    // A: groups g0:m0-7/k0-7  g1:m8-15/k0-7  g2:m0-7/k8-15  g3:m8-15/k8-15
    const int a_row  = wm * 64 + (lane & 7) + (lane & 8);
    const int a_koff = ((lane >> 4) & 1) * 16;
    // B: groups g0:n0-7/k0-7  g1:n0-7/k8-15  g2:n8-15/k0-7  g3:n8-15/k8-15
    const int b_row  = wn * 32 + (lane & 7) + ((lane >> 4) & 1) * 8;
    const int b_koff = ((lane >> 3) & 1) * 16;

    float acc[4][4][4];
    #pragma unroll
    for (int i = 0; i < 4; i++)
        #pragma unroll
        for (int j = 0; j < 4; j++)
            #pragma unroll
            for (int r = 0; r < 4; r++) acc[i][j][r] = 0.0f;

    const int nch = K >> 5;

    // ---- stage loader ----
    auto load_stage = [&](int s, int c) {
        const uint32_t dst = ld_dst + s * STAGE_B;
        const int kc = c * 32;
        const __nv_bfloat16* s0 = Ahi + a_off + kc;
        const __nv_bfloat16* s1 = Alo + a_off + kc;
        const __nv_bfloat16* s2 = Bhi + b_off + kc;
        const __nv_bfloat16* s3 = Blo + b_off + kc;
        CP_ASYNC16(dst + 0 * TILE_B,      s0);
        CP_ASYNC16(dst + 0 * TILE_B + 16, s0 + 8);
        CP_ASYNC16(dst + 1 * TILE_B,      s1);
        CP_ASYNC16(dst + 1 * TILE_B + 16, s1 + 8);
        CP_ASYNC16(dst + 2 * TILE_B,      s2);
        CP_ASYNC16(dst + 2 * TILE_B + 16, s2 + 8);
        CP_ASYNC16(dst + 3 * TILE_B,      s3);
        CP_ASYNC16(dst + 3 * TILE_B + 16, s3 + 8);
    };

    load_stage(0, 0);
    CP_COMMIT();

    for (int c = 0; c < nch; c++) {
        const int s = c & 1;
        if (c + 1 < nch) {
            load_stage(s ^ 1, c + 1);
            CP_COMMIT();
            CP_WAIT(1);
        } else {
            CP_WAIT(0);
        }
        __syncthreads();

        const uint32_t stg = sb + s * STAGE_B;
        #pragma unroll
        for (int kk = 0; kk < 2; kk++) {
            uint32_t ah[4][4], al[4][4], bh[4][2], bl[4][2];
            const uint32_t a_k = a_koff + kk * 32;
            const uint32_t b_k = b_koff + kk * 32;
            #pragma unroll
            for (int tm = 0; tm < 4; tm++) {
                const uint32_t ra = stg + (a_row + tm * 16) * ROW_B + a_k;
                LDSM4(ah[tm][0], ah[tm][1], ah[tm][2], ah[tm][3], ra);
                LDSM4(al[tm][0], al[tm][1], al[tm][2], al[tm][3], ra + TILE_B);
            }
            #pragma unroll
            for (int bp = 0; bp < 2; bp++) {
                const uint32_t rb = stg + 2 * TILE_B + (b_row + bp * 16) * ROW_B + b_k;
                LDSM4(bh[bp*2][0], bh[bp*2][1], bh[bp*2+1][0], bh[bp*2+1][1], rb);
                LDSM4(bl[bp*2][0], bl[bp*2][1], bl[bp*2+1][0], bl[bp*2+1][1], rb + TILE_B);
            }
            #pragma unroll
            for (int tm = 0; tm < 4; tm++)
                #pragma unroll
                for (int tn = 0; tn < 4; tn++) {
                    MMA16816(acc[tm][tn], ah[tm], bh[tn]);
                    MMA16816(acc[tm][tn], ah[tm], bl[tn]);
                    MMA16816(acc[tm][tn], al[tm], bh[tn]);
                }
        }
        __syncthreads();
    }

    // epilogue: direct register -> global with bias
    const int r_base = bm + wm * 64 + (lane >> 2);
    const int c_base = bn + wn * 32 + (lane & 3) * 2;
    #pragma unroll
    for (int tm = 0; tm < 4; tm++) {
        #pragma unroll
        for (int tn = 0; tn < 4; tn++) {
            const int cc = c_base + tn * 8;
            if (GUARD_N && cc >= N) continue;
            const float2 bs = *(const float2*)&bias[cc];
            const int r0 = r_base + tm * 16;
            float2 v0, v1;
            v0.x = acc[tm][tn][0] + bs.x; v0.y = acc[tm][tn][1] + bs.y;
            v1.x = acc[tm][tn][2] + bs.x; v1.y = acc[tm][tn][3] + bs.y;
            *(float2*)&C[(size_t)r0 * N + cc]       = v0;
            *(float2*)&C[(size_t)(r0 + 8) * N + cc] = v1;
        }
    }
}

// ---------------------------------------------------------------------------
// fp32 -> bf16 hi/lo split (elementwise)
// ---------------------------------------------------------------------------
__global__ void convert_hilo(const float* __restrict__ in,
                             __nv_bfloat16* __restrict__ hi,
                             __nv_bfloat16* __restrict__ lo, int n)
{
    int i = blockIdx.x * blockDim.x + threadIdx.x;
    if (i >= n) return;
    float v = in[i];
    __nv_bfloat16 h = __float2bfloat16(v);
    hi[i] = h;
    lo[i] = __float2bfloat16(v - __bfloat162float(h));
}

// ---------------------------------------------------------------------------
// W [K,N] fp32 -> Thi/Tlo [Npad,K] bf16 (transpose + split; pad rows zeroed)
// ---------------------------------------------------------------------------
__global__ void transpose_convert(int K, int N, const float* __restrict__ W,
                                  __nv_bfloat16* __restrict__ Thi,
                                  __nv_bfloat16* __restrict__ Tlo)
{
    __shared__ float tile[32][33];
    const int k0 = blockIdx.y * 32, n0 = blockIdx.x * 32;
    const int tx = threadIdx.x, ty = threadIdx.y;
    #pragma unroll
    for (int i = 0; i < 32; i += 8) {
        const int k = k0 + ty + i;
        tile[ty + i][tx] = (n0 + tx < N) ? W[(size_t)k * N + n0 + tx] : 0.0f;
    }
    __syncthreads();
    #pragma unroll
    for (int i = 0; i < 32; i += 8) {
        const int n = n0 + ty + i;
        const float v = (n < N) ? tile[tx][ty + i] : 0.0f;
        const __nv_bfloat16 h = __float2bfloat16(v);
        Thi[(size_t)n * K + k0 + tx] = h;
        Tlo[(size_t)n * K + k0 + tx] = __float2bfloat16(v - __bfloat162float(h));
    }
}

// ---------------------------------------------------------------------------
// YaRN RoPE: fp64 constants once, main kernel pure fp32
// ---------------------------------------------------------------------------
__global__ void rope_init()
{
    const int i = threadIdx.x;  // 0..31
    const double TWO_PI = 6.283185307179586;
    double freq = pow(150000.0, (double)(2 * i) / 64.0);
    double conc = 0.1 * log(32.0) + 1.0;
    double lo   = 32.0 * log(1024.0 / (32.0 * TWO_PI)) / log(150000.0);
    double hi   = 32.0 * log(1024.0 / TWO_PI) / log(150000.0);
    double ramp = ((double)i - lo) / (hi - lo);
    ramp = fmin(1.0, fmax(0.0, ramp));
    g_invf[i] = (float)(ramp / (32.0 * freq) + (1.0 - ramp) / freq);
    if (i == 0) g_conc = (float)conc;
}

__global__ void rope_kernel(float* __restrict__ qkv)
{
    const int gid = blockIdx.x * blockDim.x + threadIdx.x;
    const int i   = gid & 31;
    const int hh  = (gid >> 5) % 72;
    const int t   = gid / (32 * 72);
    if (t >= T_SEQ) return;

    const float ang = (float)t * g_invf[i];
    const float cc  = g_conc;
    const float c   = cosf(ang) * cc;
    const float s   = sinf(ang) * cc;

    const int col = (hh < 64) ? hh * 64 : 4096 + (hh - 64) * 64;
    float* p = qkv + (size_t)t * QKVD + col;
    const float x1 = p[i];
    const float x2 = p[i + 32];
    p[i]      = x1 * c - x2 * s;
    p[i + 32] = x2 * c + x1 * s;
}

// ---------------------------------------------------------------------------
// Sliding-window GQA attention with sink logits (unchanged, known-correct)
// ---------------------------------------------------------------------------
__global__ __launch_bounds__(128)
void attn_kernel(const float* __restrict__ qkv, const float* __restrict__ sinks,
                 float* __restrict__ att)
{
    __shared__ float Ks[WIN][HD + 1];
    __shared__ float wbuf[8][WIN];
    __shared__ float qs[8][HD];
    __shared__ float mxs[8], rds[8];

    const int i   = blockIdx.x;
    const int hkv = blockIdx.y;
    const int tid = threadIdx.x;

    int j0 = i - (WIN - 1);
    if (j0 < 0) j0 = 0;
    const int nk = i - j0 + 1;

    {
        const float* qp = qkv + (size_t)i * QKVD + hkv * 8 * 64;
        ((float4*)qs)[tid] = ((const float4*)qp)[tid];
    }
    for (int idx = tid; idx < nk * 64; idx += 128) {
        const int j = idx >> 6, d = idx & 63;
        Ks[j][d] = qkv[(size_t)(j0 + j) * QKVD + 4096 + hkv * 64 + d];
    }
    __syncthreads();

    float acc[8] = {0.f, 0.f, 0.f, 0.f, 0.f, 0.f, 0.f, 0.f};
    if (tid < nk) {
        #pragma unroll 8
        for (int d = 0; d < 64; d++) {
            const float kd = Ks[tid][d];
            #pragma unroll
            for (int m = 0; m < 8; m++) acc[m] = fmaf(kd, qs[m][d], acc[m]);
        }
    }
    #pragma unroll
    for (int m = 0; m < 8; m++)
        wbuf[m][tid] = (tid < nk) ? acc[m] * 0.125f : NEG_INF;
    __syncthreads();

    const int lane = tid & 31, wrp = tid >> 5;
    #pragma unroll
    for (int r = 0; r < 2; r++) {
        const int m = wrp * 2 + r;
        const float v0 = wbuf[m][lane],      v1 = wbuf[m][lane + 32];
        const float v2 = wbuf[m][lane + 64], v3 = wbuf[m][lane + 96];
        float mx = fmaxf(fmaxf(v0, v1), fmaxf(v2, v3));
        #pragma unroll
        for (int o = 16; o; o >>= 1) mx = fmaxf(mx, __shfl_xor_sync(0xffffffffu, mx, o));
        float sm = expf(v0 - mx) + expf(v1 - mx) + expf(v2 - mx) + expf(v3 - mx);
        #pragma unroll
        for (int o = 16; o; o >>= 1) sm += __shfl_xor_sync(0xffffffffu, sm, o);
        if (lane == 0) {
            const float denom = sm + expf(sinks[hkv * 8 + m] - mx);
            mxs[m] = mx;
            rds[m] = 1.0f / denom;
        }
    }
    __syncthreads();

    #pragma unroll
    for (int m = 0; m < 8; m++)
        wbuf[m][tid] = expf(wbuf[m][tid] - mxs[m]) * rds[m];
    __syncthreads();

    const int m  = tid >> 4;
    const int db = (tid & 15) * 4;
    float4 o = make_float4(0.f, 0.f, 0.f, 0.f);
    const float* vcol = qkv + 4608 + hkv * 64 + db;
    for (int j = 0; j < nk; j++) {
        const float wv = wbuf[m][j];
        const float4 v4 = *(const float4*)(vcol + (size_t)(j0 + j) * QKVD);
        o.x = fmaf(wv, v4.x, o.x);
        o.y = fmaf(wv, v4.y, o.y);
        o.z = fmaf(wv, v4.z, o.z);
        o.w = fmaf(wv, v4.w, o.w);
    }
    *(float4*)(att + (size_t)i * (NH * HD) + (hkv * 8 + m) * 64 + db) = o;
}

// ---------------------------------------------------------------------------
extern "C" void kernel_launch(void* const* d_in, const int* in_sizes, int n_in,
                              void* d_out, int out_size)
{
    (void)in_sizes; (void)n_in; (void)out_size;
    const float* x     = (const float*)d_in[0];
    const float* Wqkv  = (const float*)d_in[1];
    const float* bqkv  = (const float*)d_in[2];
    const float* Wout  = (const float*)d_in[3];
    const float* bout  = (const float*)d_in[4];
    const float* sinks = (const float*)d_in[5];
    float* out = (float*)d_out;

    void *p;
    cudaGetSymbolAddress(&p, g_qkv);  float* qkv = (float*)p;
    cudaGetSymbolAddress(&p, g_att);  float* att = (float*)p;
    cudaGetSymbolAddress(&p, g_xhi);  __nv_bfloat16* xhi = (__nv_bfloat16*)p;
    cudaGetSymbolAddress(&p, g_xlo);  __nv_bfloat16* xlo = (__nv_bfloat16*)p;
    cudaGetSymbolAddress(&p, g_w1hi); __nv_bfloat16* w1hi = (__nv_bfloat16*)p;
    cudaGetSymbolAddress(&p, g_w1lo); __nv_bfloat16* w1lo = (__nv_bfloat16*)p;
    cudaGetSymbolAddress(&p, g_w2hi); __nv_bfloat16* w2hi = (__nv_bfloat16*)p;
    cudaGetSymbolAddress(&p, g_w2lo); __nv_bfloat16* w2lo = (__nv_bfloat16*)p;
    cudaGetSymbolAddress(&p, g_ahi);  __nv_bfloat16* ahi = (__nv_bfloat16*)p;
    cudaGetSymbolAddress(&p, g_alo);  __nv_bfloat16* alo = (__nv_bfloat16*)p;

    cudaFuncSetAttribute(gemm_hmma<0>, cudaFuncAttributeMaxDynamicSharedMemorySize, GEMM_SMEM);
    cudaFuncSetAttribute(gemm_hmma<1>, cudaFuncAttributeMaxDynamicSharedMemorySize, GEMM_SMEM);

    // operand prep
    convert_hilo<<<(T_SEQ * DMODEL + 255) / 256, 256>>>(x, xhi, xlo, T_SEQ * DMODEL);
    transpose_convert<<<dim3(QKVD / 32, DMODEL / 32), dim3(32, 8)>>>(DMODEL, QKVD, Wqkv, w1hi, w1lo);
    transpose_convert<<<dim3(N2PAD / 32, (NH * HD) / 32), dim3(32, 8)>>>(NH * HD, DMODEL, Wout, w2hi, w2lo);

    // 1) qkv = x @ W_qkv + b_qkv   (HMMA, 1536x5120x2880)
    gemm_hmma<0><<<dim3(QKVD / 128, T_SEQ / 128), 256, GEMM_SMEM>>>(
        T_SEQ, QKVD, DMODEL, xhi, xlo, w1hi, w1lo, bqkv, qkv);

    // 2) RoPE
    rope_init<<<1, 32>>>();
    rope_kernel<<<(T_SEQ * 72 * 32) / 256, 256>>>(qkv);

    // 3) attention
    attn_kernel<<<dim3(T_SEQ, NKV), 128>>>(qkv, sinks, att);

    // 4) out = att @ W_out + b_out (HMMA, 1536x2880x4096, N guarded)
    convert_hilo<<<(T_SEQ * NH * HD + 255) / 256, 256>>>(att, ahi, alo, T_SEQ * NH * HD);
    gemm_hmma<1><<<dim3(N2PAD / 128, T_SEQ / 128), 256, GEMM_SMEM>>>(
        T_SEQ, DMODEL, NH * HD, ahi, alo, w2hi, w2lo, bout, out);
}